// round 3
// baseline (speedup 1.0000x reference)
#include <cuda_runtime.h>
#include <math.h>

#define NE 8
#define DM 1024
#define HN 1024
#define NT 2048

// Scratch (no allocation allowed): per-expert compaction + activation buffer.
__device__ int   g_cnt[NE];
__device__ int   g_tok[NE * NT];
__device__ float g_gate[NE * NT];
__device__ __align__(16) float g_act[NE * NT * HN];   // 64 MB fp32 scratch

__global__ void zero_cnt_kernel() {
    if (threadIdx.x < NE) g_cnt[threadIdx.x] = 0;
}

// Build per-expert token lists with combined gates (top-2; duplicates merged).
__global__ void compact_kernel(const float* __restrict__ p, const int* __restrict__ idx) {
    int t = blockIdx.x * blockDim.x + threadIdx.x;
    if (t >= NT) return;
    int e0 = idx[2 * t], e1 = idx[2 * t + 1];
    float p0 = p[2 * t], p1 = p[2 * t + 1];
    if (e0 == e1) {
        int s = atomicAdd(&g_cnt[e0], 1);
        g_tok[e0 * NT + s] = t;
        g_gate[e0 * NT + s] = p0 + p1;
    } else {
        int s0 = atomicAdd(&g_cnt[e0], 1);
        g_tok[e0 * NT + s0] = t;
        g_gate[e0 * NT + s0] = p0;
        int s1 = atomicAdd(&g_cnt[e1], 1);
        g_tok[e1 * NT + s1] = t;
        g_gate[e1 * NT + s1] = p1;
    }
}

// ---------------- Pass 1: A = gelu(Xg @ Wu_h) * (Xg @ Wu_g + 1) ----------------
// CTA tile 128(m) x 64(n), BK=16, 256 threads, micro-tile 8x4, dual accumulators.
#define P1_BM 128
#define P1_BN 64
#define P1_BK 16

__global__ __launch_bounds__(256) void up_kernel(const float* __restrict__ x,
                                                 const float* __restrict__ wu) {
    int e = blockIdx.z;
    int R = g_cnt[e];
    int m0 = blockIdx.y * P1_BM;
    if (m0 >= R) return;
    int j0 = blockIdx.x * P1_BN;
    int tid = threadIdx.x;
    int tx = tid & 15, ty = tid >> 4;

    __shared__ float Xs[P1_BK][P1_BM + 1];   // scalar stores only
    __shared__ float Bh[P1_BK][P1_BN + 4];   // +4 pad: rows 16B-aligned for STS.128
    __shared__ float Bg[P1_BK][P1_BN + 4];
    __shared__ int   toks[P1_BM];

    if (tid < P1_BM) {
        int m = m0 + tid;
        toks[tid] = (m < R) ? g_tok[e * NT + m] : -1;
    }
    __syncthreads();

    float ah[8][4] = {}, ag[8][4] = {};
    const float* wue = wu + (size_t)e * DM * (2 * HN);

    for (int k0 = 0; k0 < DM; k0 += P1_BK) {
        // X tile: 128 rows x 16 k, float4 along k, transpose-scatter into Xs
        #pragma unroll
        for (int u = 0; u < 2; u++) {
            int id = tid + 256 * u;          // 0..511
            int m  = id >> 2;                // 0..127
            int q  = (id & 3) << 2;          // 0,4,8,12
            int t  = toks[m];
            float4 v = make_float4(0.f, 0.f, 0.f, 0.f);
            if (t >= 0) v = *(const float4*)&x[(size_t)t * DM + k0 + q];
            Xs[q + 0][m] = v.x; Xs[q + 1][m] = v.y;
            Xs[q + 2][m] = v.z; Xs[q + 3][m] = v.w;
        }
        // Weight tiles: 16 k x 64 n, float4 along n (one per thread per half)
        {
            int kk = tid >> 4;               // 0..15
            int j4 = (tid & 15) << 2;        // 0..60
            const float* wrow = wue + (size_t)(k0 + kk) * (2 * HN) + j0 + j4;
            float4 vh = *(const float4*)&wrow[0];
            float4 vg = *(const float4*)&wrow[HN];
            *(float4*)&Bh[kk][j4] = vh;
            *(float4*)&Bg[kk][j4] = vg;
        }
        __syncthreads();
        #pragma unroll
        for (int kk = 0; kk < P1_BK; kk++) {
            float av[8], bh[4], bg[4];
            #pragma unroll
            for (int i = 0; i < 8; i++) av[i] = Xs[kk][ty + 16 * i];
            #pragma unroll
            for (int j = 0; j < 4; j++) {
                bh[j] = Bh[kk][tx + 16 * j];
                bg[j] = Bg[kk][tx + 16 * j];
            }
            #pragma unroll
            for (int i = 0; i < 8; i++)
                #pragma unroll
                for (int j = 0; j < 4; j++) {
                    ah[i][j] += av[i] * bh[j];
                    ag[i][j] += av[i] * bg[j];
                }
        }
        __syncthreads();
    }

    #pragma unroll
    for (int i = 0; i < 8; i++) {
        int m = m0 + ty + 16 * i;
        if (m >= R) continue;
        size_t base = ((size_t)e * NT + m) * HN + j0;
        #pragma unroll
        for (int j = 0; j < 4; j++) {
            float h = ah[i][j], g = ag[i][j];
            float a = 0.5f * h * (1.f + erff(h * 0.70710678118654752f)) * (g + 1.f);
            g_act[base + tx + 16 * j] = a;
        }
    }
}

// ---------------- Pass 2: y[tok,:] += gate * (A @ Wd) ----------------
// CTA tile 128x128, BK=16, 256 threads, micro-tile 8x8, atomic combine.
#define P2_BM 128
#define P2_BN 128
#define P2_BK 16

__global__ __launch_bounds__(256) void down_kernel(const float* __restrict__ wd,
                                                   float* __restrict__ y) {
    int e = blockIdx.z;
    int R = g_cnt[e];
    int m0 = blockIdx.y * P2_BM;
    if (m0 >= R) return;
    int d0 = blockIdx.x * P2_BN;
    int tid = threadIdx.x;
    int tx = tid & 15, ty = tid >> 4;

    __shared__ float As[P2_BK][P2_BM + 1];   // scalar stores only
    __shared__ float Bs[P2_BK][P2_BN + 4];   // +4 pad: rows 16B-aligned for STS.128
    __shared__ int   toks[P2_BM];
    __shared__ float gts[P2_BM];

    if (tid < P2_BM) {
        int m = m0 + tid;
        toks[tid] = (m < R) ? g_tok[e * NT + m] : -1;
        gts[tid]  = (m < R) ? g_gate[e * NT + m] : 0.f;
    }
    __syncthreads();

    float acc[8][8] = {};
    const float* wde = wd + (size_t)e * HN * DM;

    for (int k0 = 0; k0 < HN; k0 += P2_BK) {
        // A tile: 128 rows x 16 k, transpose-scatter (k contiguous in g_act)
        #pragma unroll
        for (int u = 0; u < 2; u++) {
            int id = tid + 256 * u;
            int m  = id >> 2;
            int q  = (id & 3) << 2;
            float4 v = make_float4(0.f, 0.f, 0.f, 0.f);
            if (toks[m] >= 0)
                v = *(const float4*)&g_act[((size_t)e * NT + m0 + m) * HN + k0 + q];
            As[q + 0][m] = v.x; As[q + 1][m] = v.y;
            As[q + 2][m] = v.z; As[q + 3][m] = v.w;
        }
        // Wd tile: 16 k x 128 d, d contiguous
        #pragma unroll
        for (int u = 0; u < 2; u++) {
            int id = tid + 256 * u;          // 0..511
            int kk = id >> 5;                // 0..15
            int d4 = (id & 31) << 2;         // 0..124
            *(float4*)&Bs[kk][d4] =
                *(const float4*)&wde[(size_t)(k0 + kk) * DM + d0 + d4];
        }
        __syncthreads();
        #pragma unroll
        for (int kk = 0; kk < P2_BK; kk++) {
            float av[8], bv[8];
            #pragma unroll
            for (int i = 0; i < 8; i++) av[i] = As[kk][ty + 16 * i];
            #pragma unroll
            for (int j = 0; j < 8; j++) bv[j] = Bs[kk][tx + 16 * j];
            #pragma unroll
            for (int i = 0; i < 8; i++)
                #pragma unroll
                for (int j = 0; j < 8; j++)
                    acc[i][j] += av[i] * bv[j];
        }
        __syncthreads();
    }

    #pragma unroll
    for (int i = 0; i < 8; i++) {
        int mi = ty + 16 * i;
        if (m0 + mi >= R) continue;
        int   t = toks[mi];
        float g = gts[mi];
        size_t base = (size_t)t * DM + d0;
        #pragma unroll
        for (int j = 0; j < 8; j++)
            atomicAdd(&y[base + tx + 16 * j], g * acc[i][j]);
    }
}

extern "C" void kernel_launch(void* const* d_in, const int* in_sizes, int n_in,
                              void* d_out, int out_size) {
    const float* x   = (const float*)d_in[0];
    const float* p   = (const float*)d_in[1];
    const int*   idx = (const int*)d_in[2];
    const float* wu  = (const float*)d_in[3];
    const float* wd  = (const float*)d_in[4];
    float* y = (float*)d_out;

    cudaMemsetAsync(y, 0, (size_t)out_size * sizeof(float));
    zero_cnt_kernel<<<1, 32>>>();
    compact_kernel<<<(NT + 255) / 256, 256>>>(p, idx);

    dim3 g1(HN / P1_BN, NT / P1_BM, NE);
    up_kernel<<<g1, 256>>>(x, wu);

    dim3 g2(DM / P2_BN, NT / P2_BM, NE);
    down_kernel<<<g2, 256>>>(wd, y);
}

// round 5
// speedup vs baseline: 1.8243x; 1.8243x over previous
#include <cuda_runtime.h>
#include <cstdint>
#include <math.h>

#define NE 8
#define DM 1024
#define HN 1024
#define NT 2048

// ---------------- scratch (no allocation allowed) ----------------
__device__ int   g_cnt[NE];
__device__ int   g_tok[NE * NT];
__device__ float g_gate[NE * NT];
__device__ __align__(16) float g_uh[NE * NT * 2 * HN];   // 128 MB: up-proj result
__device__ __align__(16) float g_act[NE * NT * HN];      // 64 MB: GLU output

__device__ __forceinline__ uint32_t f2tf32(float f) {
    uint32_t u; asm("cvt.rna.tf32.f32 %0, %1;" : "=r"(u) : "f"(f)); return u;
}

__device__ __forceinline__ void mma_tf32(float d[4], const uint32_t a[4], const uint32_t b[2]) {
    asm volatile("mma.sync.aligned.m16n8k8.row.col.f32.tf32.tf32.f32 "
                 "{%0,%1,%2,%3}, {%4,%5,%6,%7}, {%8,%9}, {%0,%1,%2,%3};"
                 : "+f"(d[0]), "+f"(d[1]), "+f"(d[2]), "+f"(d[3])
                 : "r"(a[0]), "r"(a[1]), "r"(a[2]), "r"(a[3]), "r"(b[0]), "r"(b[1]));
}

// ---------------- setup ----------------
__global__ void zero_cnt_kernel() {
    if (threadIdx.x < NE) g_cnt[threadIdx.x] = 0;
}

__global__ void compact_kernel(const float* __restrict__ p, const int* __restrict__ idx) {
    int t = blockIdx.x * blockDim.x + threadIdx.x;
    if (t >= NT) return;
    int e0 = idx[2 * t], e1 = idx[2 * t + 1];
    float p0 = p[2 * t], p1 = p[2 * t + 1];
    if (e0 == e1) {
        int s = atomicAdd(&g_cnt[e0], 1);
        g_tok[e0 * NT + s] = t; g_gate[e0 * NT + s] = p0 + p1;
    } else {
        int s0 = atomicAdd(&g_cnt[e0], 1);
        g_tok[e0 * NT + s0] = t; g_gate[e0 * NT + s0] = p0;
        int s1 = atomicAdd(&g_cnt[e1], 1);
        g_tok[e1 * NT + s1] = t; g_gate[e1 * NT + s1] = p1;
    }
}

// ---------------- shared GEMM machinery ----------------
// CTA tile 128(m) x 128(n), BK=32. 8 warps as 2(m) x 4(n); warp tile 64x32.
// smem stride 36 floats: fragment-load banks = (4*row + k) % 32, conflict-free.
#define SSTR 36

struct Frag { float acc[4][4][4]; };  // [mf][nf][c]

__device__ __forceinline__ void gemm_tile_compute(
    const float (*As)[SSTR], const float (*Bs)[SSTR],
    int warpM, int warpN, int gid, int tig, Frag& F)
{
    #pragma unroll
    for (int ks = 0; ks < 4; ks++) {
        int kb = ks * 8;
        uint32_t af[4][4];
        #pragma unroll
        for (int mf = 0; mf < 4; mf++) {
            int r0 = warpM + mf * 16 + gid;
            af[mf][0] = __float_as_uint(As[r0][kb + tig]);
            af[mf][1] = __float_as_uint(As[r0 + 8][kb + tig]);
            af[mf][2] = __float_as_uint(As[r0][kb + tig + 4]);
            af[mf][3] = __float_as_uint(As[r0 + 8][kb + tig + 4]);
        }
        uint32_t bf[4][2];
        #pragma unroll
        for (int nf = 0; nf < 4; nf++) {
            int n0 = warpN + nf * 8 + gid;
            bf[nf][0] = __float_as_uint(Bs[n0][kb + tig]);
            bf[nf][1] = __float_as_uint(Bs[n0][kb + tig + 4]);
        }
        #pragma unroll
        for (int mf = 0; mf < 4; mf++)
            #pragma unroll
            for (int nf = 0; nf < 4; nf++)
                mma_tf32(F.acc[mf][nf], af[mf], bf[nf]);
    }
}

// ---------------- Pass 1: UH = Xg @ Wu (N = 2*HN = 2048 cols) ----------------
__global__ __launch_bounds__(256, 2) void up_kernel(const float* __restrict__ x,
                                                    const float* __restrict__ wu) {
    int e = blockIdx.z;
    int R = g_cnt[e];
    int m0 = blockIdx.y * 128;
    if (m0 >= R) return;
    int j0 = blockIdx.x * 128;
    int tid = threadIdx.x;
    int w = tid >> 5, lane = tid & 31;
    int gid = lane >> 2, tig = lane & 3;
    int warpM = (w & 1) * 64, warpN = (w >> 1) * 32;

    __shared__ float As[128][SSTR];
    __shared__ float Bs[128][SSTR];
    __shared__ int toks[128];

    if (tid < 128) { int m = m0 + tid; toks[tid] = (m < R) ? g_tok[e * NT + m] : -1; }
    __syncthreads();

    Frag F;
    #pragma unroll
    for (int mf = 0; mf < 4; mf++)
        #pragma unroll
        for (int nf = 0; nf < 4; nf++)
            #pragma unroll
            for (int c = 0; c < 4; c++) F.acc[mf][nf][c] = 0.f;

    const float* wue = wu + (size_t)e * DM * (2 * HN);

    for (int k0 = 0; k0 < DM; k0 += 32) {
        // global loads into regs
        float4 av[4];
        #pragma unroll
        for (int u = 0; u < 4; u++) {
            int id = tid + 256 * u;             // 0..1023
            int m = id >> 3, q = (id & 7) * 4;
            int t = toks[m];
            av[u] = (t >= 0) ? *(const float4*)&x[(size_t)t * DM + k0 + q]
                             : make_float4(0.f, 0.f, 0.f, 0.f);
        }
        float4 bv[4];
        #pragma unroll
        for (int u = 0; u < 4; u++) {
            int id = tid + 256 * u;
            int kk = id >> 5, n4 = (id & 31) * 4;
            bv[u] = *(const float4*)&wue[(size_t)(k0 + kk) * (2 * HN) + j0 + n4];
        }
        __syncthreads();   // previous chunk's smem reads complete
        #pragma unroll
        for (int u = 0; u < 4; u++) {
            int id = tid + 256 * u;
            int m = id >> 3, q = (id & 7) * 4;
            float* dst = &As[m][q];
            dst[0] = __uint_as_float(f2tf32(av[u].x));
            dst[1] = __uint_as_float(f2tf32(av[u].y));
            dst[2] = __uint_as_float(f2tf32(av[u].z));
            dst[3] = __uint_as_float(f2tf32(av[u].w));
        }
        #pragma unroll
        for (int u = 0; u < 4; u++) {
            int id = tid + 256 * u;
            int kk = id >> 5, n4 = (id & 31) * 4;
            const float* f = &bv[u].x;
            #pragma unroll
            for (int i = 0; i < 4; i++)
                Bs[n4 + i][kk] = __uint_as_float(f2tf32(f[i]));
        }
        __syncthreads();
        gemm_tile_compute(As, Bs, warpM, warpN, gid, tig, F);
    }

    // epilogue: store UH tile (rows beyond R hold garbage; GLU kernel masks)
    size_t base = ((size_t)e * NT + m0) * (2 * HN) + j0;
    #pragma unroll
    for (int mf = 0; mf < 4; mf++) {
        int r0 = warpM + mf * 16 + gid;
        #pragma unroll
        for (int nf = 0; nf < 4; nf++) {
            int c0 = warpN + nf * 8 + 2 * tig;
            *(float2*)&g_uh[base + (size_t)r0 * (2 * HN) + c0] =
                make_float2(F.acc[mf][nf][0], F.acc[mf][nf][1]);
            *(float2*)&g_uh[base + (size_t)(r0 + 8) * (2 * HN) + c0] =
                make_float2(F.acc[mf][nf][2], F.acc[mf][nf][3]);
        }
    }
}

// ---------------- GLU: act = gelu(h) * (g + 1) ----------------
__global__ __launch_bounds__(256) void glu_kernel() {
    int e = blockIdx.x >> 11;          // 2048 rows per expert
    int m = blockIdx.x & 2047;
    if (m >= g_cnt[e]) return;
    size_t ub = ((size_t)e * NT + m) * (2 * HN);
    size_t ab = ((size_t)e * NT + m) * HN;
    int j = threadIdx.x * 4;
    float4 h4 = *(const float4*)&g_uh[ub + j];
    float4 g4 = *(const float4*)&g_uh[ub + HN + j];
    float4 o;
    o.x = 0.5f * h4.x * (1.f + erff(h4.x * 0.70710678118654752f)) * (g4.x + 1.f);
    o.y = 0.5f * h4.y * (1.f + erff(h4.y * 0.70710678118654752f)) * (g4.y + 1.f);
    o.z = 0.5f * h4.z * (1.f + erff(h4.z * 0.70710678118654752f)) * (g4.z + 1.f);
    o.w = 0.5f * h4.w * (1.f + erff(h4.w * 0.70710678118654752f)) * (g4.w + 1.f);
    *(float4*)&g_act[ab + j] = o;
}

// ---------------- Pass 2: y[tok,:] += gate * (act @ Wd) ----------------
__global__ __launch_bounds__(256, 2) void down_kernel(const float* __restrict__ wd,
                                                      float* __restrict__ y) {
    int e = blockIdx.z;
    int R = g_cnt[e];
    int m0 = blockIdx.y * 128;
    if (m0 >= R) return;
    int d0 = blockIdx.x * 128;
    int tid = threadIdx.x;
    int w = tid >> 5, lane = tid & 31;
    int gid = lane >> 2, tig = lane & 3;
    int warpM = (w & 1) * 64, warpN = (w >> 1) * 32;

    __shared__ float As[128][SSTR];
    __shared__ float Bs[128][SSTR];
    __shared__ int toks[128];
    __shared__ float gts[128];

    if (tid < 128) {
        int m = m0 + tid;
        toks[tid] = (m < R) ? g_tok[e * NT + m] : -1;
        gts[tid]  = (m < R) ? g_gate[e * NT + m] : 0.f;
    }
    __syncthreads();

    Frag F;
    #pragma unroll
    for (int mf = 0; mf < 4; mf++)
        #pragma unroll
        for (int nf = 0; nf < 4; nf++)
            #pragma unroll
            for (int c = 0; c < 4; c++) F.acc[mf][nf][c] = 0.f;

    const float* wde = wd + (size_t)e * HN * DM;

    for (int k0 = 0; k0 < HN; k0 += 32) {
        float4 av[4];
        #pragma unroll
        for (int u = 0; u < 4; u++) {
            int id = tid + 256 * u;
            int m = id >> 3, q = (id & 7) * 4;
            av[u] = (toks[m] >= 0)
                ? *(const float4*)&g_act[((size_t)e * NT + m0 + m) * HN + k0 + q]
                : make_float4(0.f, 0.f, 0.f, 0.f);
        }
        float4 bv[4];
        #pragma unroll
        for (int u = 0; u < 4; u++) {
            int id = tid + 256 * u;
            int kk = id >> 5, n4 = (id & 31) * 4;
            bv[u] = *(const float4*)&wde[(size_t)(k0 + kk) * DM + d0 + n4];
        }
        __syncthreads();
        #pragma unroll
        for (int u = 0; u < 4; u++) {
            int id = tid + 256 * u;
            int m = id >> 3, q = (id & 7) * 4;
            float* dst = &As[m][q];
            dst[0] = __uint_as_float(f2tf32(av[u].x));
            dst[1] = __uint_as_float(f2tf32(av[u].y));
            dst[2] = __uint_as_float(f2tf32(av[u].z));
            dst[3] = __uint_as_float(f2tf32(av[u].w));
        }
        #pragma unroll
        for (int u = 0; u < 4; u++) {
            int id = tid + 256 * u;
            int kk = id >> 5, n4 = (id & 31) * 4;
            const float* f = &bv[u].x;
            #pragma unroll
            for (int i = 0; i < 4; i++)
                Bs[n4 + i][kk] = __uint_as_float(f2tf32(f[i]));
        }
        __syncthreads();
        gemm_tile_compute(As, Bs, warpM, warpN, gid, tig, F);
    }

    // epilogue: gated atomic combine
    #pragma unroll
    for (int mf = 0; mf < 4; mf++) {
        int r0 = warpM + mf * 16 + gid;
        #pragma unroll
        for (int half = 0; half < 2; half++) {
            int r = r0 + 8 * half;
            if (m0 + r >= R) continue;
            int   t = toks[r];
            float g = gts[r];
            size_t base = (size_t)t * DM + d0;
            #pragma unroll
            for (int nf = 0; nf < 4; nf++) {
                int c0 = warpN + nf * 8 + 2 * tig;
                atomicAdd(&y[base + c0],     g * F.acc[mf][nf][2 * half]);
                atomicAdd(&y[base + c0 + 1], g * F.acc[mf][nf][2 * half + 1]);
            }
        }
    }
}

// ---------------- host ----------------
extern "C" void kernel_launch(void* const* d_in, const int* in_sizes, int n_in,
                              void* d_out, int out_size) {
    const float* x   = (const float*)d_in[0];
    const float* p   = (const float*)d_in[1];
    const int*   idx = (const int*)d_in[2];
    const float* wu  = (const float*)d_in[3];
    const float* wd  = (const float*)d_in[4];
    float* y = (float*)d_out;

    cudaMemsetAsync(y, 0, (size_t)out_size * sizeof(float));
    zero_cnt_kernel<<<1, 32>>>();
    compact_kernel<<<(NT + 255) / 256, 256>>>(p, idx);

    up_kernel<<<dim3(2 * HN / 128, NT / 128, NE), 256>>>(x, wu);
    glu_kernel<<<NE * NT, 256>>>();
    down_kernel<<<dim3(DM / 128, NT / 128, NE), 256>>>(wd, y);
}